// round 10
// baseline (speedup 1.0000x reference)
#include <cuda_runtime.h>

// ---------------------------------------------------------------------------
// GMMNet, 2 pixels/thread, packed f32x2 (FFMA2).
// R10: LDCU.128 pair-loaded weights for the three big matrices
// (MU_W1, MU_W2, SG_W1) with the dot-product input array st[24] as the
// CANONICAL state storage (x | mu->mun in place | rho) -> no marshaling
// copies, no register blowup. Small matrices stay scalar (R6 code).
// ---------------------------------------------------------------------------

typedef unsigned long long u64;

namespace {
constexpr int Bn = 4, Sn = 8, Cn = 3, Hn = 384, Wn = 384, Kn = 5, CKn = 15;
constexpr int HWn  = Hn * Wn;            // 147456
constexpr int NPIX = Bn * HWn;           // 589824
constexpr int HALF = NPIX / 2;           // 294912

// padded constant layout (u64 element offsets; big W rows start even)
constexpr int PI_W1 = 0;     // 5 x 10, stride 10 (scalar)
constexpr int PI_B1 = 50;    // 5
constexpr int PI_W2 = 56;    // 5 x 5, stride 6 (scalar)
constexpr int PI_B2 = 86;    // 5
constexpr int MU_W1 = 92;    // 15 x 23, stride 24 (paired)
constexpr int MU_B1 = 452;   // 15
constexpr int MU_W2 = 468;   // 15 x 15, stride 16 (paired)
constexpr int MU_B2 = 708;   // 15
constexpr int SG_W1 = 724;   // 5 x 23, stride 24 (paired)
constexpr int SG_B1 = 844;   // 5
constexpr int SG_W2 = 850;   // 5 x 5, stride 6 (scalar)
constexpr int SG_B2 = 880;   // 5
constexpr int GA_W1 = 886;   // 5 x 5, stride 6 (scalar)
constexpr int GA_B1 = 916;   // 5
constexpr int GA_W2 = 922;   // 1 x 5, stride 6 (scalar)
constexpr int GA_B2 = 928;   // 1
constexpr int NPAD  = 930;   // even

constexpr float L2E = 1.4426950408889634f;
}

__constant__ __align__(16) u64 cw2[NPAD];
__device__ u64 g_staging[NPAD];

// ---- packed helpers ---------------------------------------------------------
__device__ __forceinline__ u64 pk(float lo, float hi) {
    u64 r; asm("mov.b64 %0, {%1, %2};" : "=l"(r) : "f"(lo), "f"(hi)); return r;
}
__device__ __forceinline__ void upk(u64 v, float& lo, float& hi) {
    asm("mov.b64 {%0, %1}, %2;" : "=f"(lo), "=f"(hi) : "l"(v));
}
__device__ __forceinline__ u64 fma2(u64 a, u64 b, u64 c) {
    u64 d; asm("fma.rn.f32x2 %0, %1, %2, %3;" : "=l"(d) : "l"(a), "l"(b), "l"(c)); return d;
}
__device__ __forceinline__ u64 mul2(u64 a, u64 b) {
    u64 d; asm("mul.rn.f32x2 %0, %1, %2;" : "=l"(d) : "l"(a), "l"(b)); return d;
}
__device__ __forceinline__ u64 add2(u64 a, u64 b) {
    u64 d; asm("add.rn.f32x2 %0, %1, %2;" : "=l"(d) : "l"(a), "l"(b)); return d;
}
__device__ __forceinline__ float ex2f(float x) {
    float y; asm("ex2.approx.f32 %0, %1;" : "=f"(y) : "f"(x)); return y;
}
__device__ __forceinline__ float rcpf(float x) {
    float y; asm("rcp.approx.f32 %0, %1;" : "=f"(y) : "f"(x)); return y;
}
__device__ __forceinline__ float tanhf_a(float x) {
    float y; asm("tanh.approx.f32 %0, %1;" : "=f"(y) : "f"(x)); return y;
}
__device__ __forceinline__ u64 ex2_2(u64 x) {
    float lo, hi; upk(x, lo, hi); return pk(ex2f(lo), ex2f(hi));
}
__device__ __forceinline__ u64 rcp_2(u64 x) {
    float lo, hi; upk(x, lo, hi); return pk(rcpf(lo), rcpf(hi));
}
__device__ __forceinline__ u64 tanh_2(u64 x) {
    float lo, hi; upk(x, lo, hi); return pk(tanhf_a(lo), tanhf_a(hi));
}
__device__ __forceinline__ u64 relu2(u64 x) {
    float lo, hi; upk(x, lo, hi);
    return pk(fmaxf(lo, 0.f), fmaxf(hi, 0.f));
}
__device__ __forceinline__ u64 min0_2(u64 x) {
    float lo, hi; upk(x, lo, hi);
    return pk(fminf(lo, 0.f), fminf(hi, 0.f));
}

// paired-row dot against an unrolled register array (no copies)
template<int NPair>
__device__ __forceinline__ u64 dotrow(int base, const u64* in, u64 acc) {
    const ulonglong2* wp = reinterpret_cast<const ulonglong2*>(&cw2[base]);
#pragma unroll
    for (int j = 0; j < NPair; j++) {
        const ulonglong2 w = wp[j];
        acc = fma2(w.x, in[2 * j],     acc);
        acc = fma2(w.y, in[2 * j + 1], acc);
    }
    return acc;
}

// ---- weight duplication into padded layout ------------------------------------
struct WPtrs { const float* p[16]; };

__global__ void dup_weights(WPtrs w) {
    const int d = blockIdx.x * blockDim.x + threadIdx.x;
    if (d >= NPAD) return;
    struct S { int dst, rows, cols, stride; float sc; };
    constexpr float H = 0.5f;
    const S seg[16] = {
        {PI_W1, 5, 10, 10,  1.f }, {PI_B1, 5, 1, 1,  1.f },
        {PI_W2, 5,  5,  6,  L2E }, {PI_B2, 5, 1, 1,  L2E },
        {MU_W1,15, 23, 24,  1.f }, {MU_B1,15, 1, 1,  1.f },
        {MU_W2,15, 15, 16,  H   }, {MU_B2,15, 1, 1,  H   },
        {SG_W1, 5, 23, 24,  1.f }, {SG_B1, 5, 1, 1,  1.f },
        {SG_W2, 5,  5,  6, -L2E }, {SG_B2, 5, 1, 1, -L2E },
        {GA_W1, 5,  5,  6,  1.f }, {GA_B1, 5, 1, 1,  1.f },
        {GA_W2, 1,  5,  6,  H   }, {GA_B2, 1, 1, 1,  H   },
    };
    float v = 0.f;
    for (int s = 0; s < 16; s++) {
        const int end = seg[s].dst + seg[s].rows * seg[s].stride;
        if (d >= seg[s].dst && d < end) {
            const int r = (d - seg[s].dst) / seg[s].stride;
            const int c = (d - seg[s].dst) % seg[s].stride;
            if (c < seg[s].cols)
                v = w.p[s][r * seg[s].cols + c] * seg[s].sc;
            break;
        }
    }
    g_staging[d] = pk(v, v);
}

// ---- main kernel --------------------------------------------------------------
__global__ void __launch_bounds__(256)
gmm2_kernel(const float* __restrict__ frames,   // [B,S,C,H,W]
            const float* __restrict__ mu0,      // [B,CK,H,W]
            float* __restrict__ out)            // [B,S,1,H,W]
{
    const int t = blockIdx.x * blockDim.x + threadIdx.x;
    if (t >= HALF) return;

    const int b0 = t / HWn,  hw0 = t - b0 * HWn;
    const int p1 = t + HALF;
    const int b1 = p1 / HWn, hw1 = p1 - b1 * HWn;

    const float* f0 = frames + (b0 * Sn * Cn) * HWn + hw0;
    const float* f1 = frames + (b1 * Sn * Cn) * HWn + hw1;
    const float* m0 = mu0 + (b0 * CKn) * HWn + hw0;
    const float* m1 = mu0 + (b1 * CKn) * HWn + hw1;
    float* o0 = out + (b0 * Sn) * HWn + hw0;
    float* o1 = out + (b1 * Sn) * HWn + hw1;

    const u64 HALF2  = pk(0.5f, 0.5f);
    const u64 NEG12  = pk(-1.0f, -1.0f);
    const u64 C02    = pk(0.06349363593424097f, 0.06349363593424097f);   // (2pi)^-1.5
    const u64 NHL2E2 = pk(-0.7213475204444817f, -0.7213475204444817f);   // -0.5*log2e
    const u64 Z2     = 0ULL;

    // canonical state array st[24]: [0..2]=x, [3..17]=mu (becomes mun in
    // place), [18..22]=rho, [23]=pad. Plus pi, r2s, cf.
    u64 st[24];
    u64 pi[Kn], r2s[Kn], cf[Kn];
#pragma unroll
    for (int k = 0; k < Kn; k++) { pi[k] = pk(0.2f, 0.2f); r2s[k] = NHL2E2; cf[k] = C02; }
#pragma unroll
    for (int i = 0; i < CKn; i++) st[3 + i] = pk(m0[i * HWn], m1[i * HWn]);
    st[23] = Z2;

#pragma unroll 1
    for (int s = 0; s < Sn; s++) {
#pragma unroll
        for (int c = 0; c < Cn; c++)
            st[c] = pk(f0[(s * Cn + c) * HWn], f1[(s * Cn + c) * HWn]);

        // ---- density 1, alpha, rho (rho -> st[18+k]) -----------------------
        u64 alpha[Kn];
#pragma unroll
        for (int k = 0; k < Kn; k++) {
            u64 t0 = fma2(st[3 + k * Cn + 0], NEG12, st[0]);
            u64 d  = mul2(t0, t0);
            u64 t1 = fma2(st[3 + k * Cn + 1], NEG12, st[1]);
            d = fma2(t1, t1, d);
            u64 t2 = fma2(st[3 + k * Cn + 2], NEG12, st[2]);
            d = fma2(t2, t2, d);
            const u64 dens = mul2(cf[k], ex2_2(mul2(d, r2s[k])));
            alpha[k]   = mul2(pi[k], dens);
            st[18 + k] = mul2(alpha[k], dens);   // rho
        }

        // ---- pi MLP -> softmax (scalar weights; W2 pre-scaled by log2e) ----
        u64 hp[Kn];
#pragma unroll
        for (int o = 0; o < Kn; o++) {
            u64 a = cw2[PI_B1 + o];
#pragma unroll
            for (int i = 0; i < Kn; i++) a = fma2(cw2[PI_W1 + o * 10 + i],     pi[i],    a);
#pragma unroll
            for (int i = 0; i < Kn; i++) a = fma2(cw2[PI_W1 + o * 10 + 5 + i], alpha[i], a);
            hp[o] = relu2(a);
        }
        u64 pin[Kn], esum = 0ULL;
#pragma unroll
        for (int o = 0; o < Kn; o++) {
            u64 a = cw2[PI_B2 + o];
#pragma unroll
            for (int i = 0; i < Kn; i++) a = fma2(cw2[PI_W2 + o * 6 + i], hp[i], a);
            pin[o] = ex2_2(a);
            esum   = add2(esum, pin[o]);
        }
        {
            const u64 einv = rcp_2(esum);
#pragma unroll
            for (int k = 0; k < Kn; k++) pin[k] = mul2(pin[k], einv);
        }

        // ---- mu MLP (paired weights; W2 pre-scaled by 0.5) ------------------
        u64 hm[16];
#pragma unroll
        for (int o = 0; o < CKn; o++)
            hm[o] = relu2(dotrow<12>(MU_W1 + o * 24, st, cw2[MU_B1 + o]));
        hm[15] = Z2;
        // layer 2 writes mun INTO st[3+o] (mu is dead after layer 1)
#pragma unroll
        for (int o = 0; o < CKn; o++)
            st[3 + o] = fma2(tanh_2(dotrow<8>(MU_W2 + o * 16, hm, cw2[MU_B2 + o])),
                             HALF2, HALF2);

        // ---- sigma MLP (paired L1; scalar L2 pre-scaled by -log2e) ----------
        u64 hs[Kn];
#pragma unroll
        for (int o = 0; o < Kn; o++)
            hs[o] = relu2(dotrow<12>(SG_W1 + o * 24, st, cw2[SG_B1 + o]));
#pragma unroll
        for (int o = 0; o < Kn; o++) {
            u64 a = cw2[SG_B2 + o];
#pragma unroll
            for (int i = 0; i < Kn; i++) a = fma2(cw2[SG_W2 + o * 6 + i], hs[i], a);
            const u64 rin = ex2_2(min0_2(a));       // 1/sigma
            const u64 rr  = mul2(rin, rin);         // 1/sigma^2
            r2s[o] = mul2(rr, NHL2E2);
            cf[o]  = mul2(mul2(rin, C02), rr);      // C0/sigma^3
        }

        // ---- density 2 (mun in st), g = pi_new * dens2 ----------------------
        u64 g[Kn];
#pragma unroll
        for (int k = 0; k < Kn; k++) {
            u64 t0 = fma2(st[3 + k * Cn + 0], NEG12, st[0]);
            u64 d  = mul2(t0, t0);
            u64 t1 = fma2(st[3 + k * Cn + 1], NEG12, st[1]);
            d = fma2(t1, t1, d);
            u64 t2 = fma2(st[3 + k * Cn + 2], NEG12, st[2]);
            d = fma2(t2, t2, d);
            g[k] = mul2(pin[k], mul2(cf[k], ex2_2(mul2(d, r2s[k]))));
        }

        // ---- gamma MLP (scalar; W2/B2 pre-scaled by 0.5) ---------------------
        u64 hg[Kn];
#pragma unroll
        for (int o = 0; o < Kn; o++) {
            u64 a = cw2[GA_B1 + o];
#pragma unroll
            for (int i = 0; i < Kn; i++) a = fma2(cw2[GA_W1 + o * 6 + i], g[i], a);
            hg[o] = relu2(a);
        }
        u64 ga = cw2[GA_B2];
#pragma unroll
        for (int i = 0; i < Kn; i++) ga = fma2(cw2[GA_W2 + i], hg[i], ga);
        {
            float al, ah; upk(ga, al, ah);
            o0[s * HWn] = fmaf(tanhf_a(al), 0.5f, 0.5f);
            o1[s * HWn] = fmaf(tanhf_a(ah), 0.5f, 0.5f);
        }

        // ---- carry (mu already in st) ----------------------------------------
#pragma unroll
        for (int k = 0; k < Kn; k++) pi[k] = pin[k];
    }
}

extern "C" void kernel_launch(void* const* d_in, const int* in_sizes, int n_in,
                              void* d_out, int out_size)
{
    (void)in_sizes; (void)n_in; (void)out_size;
    const float* frames = (const float*)d_in[0];
    const float* mu0    = (const float*)d_in[2];   // d_in[1] = targets (unused)

    WPtrs w;
    for (int i = 0; i < 16; i++) w.p[i] = (const float*)d_in[3 + i];

    dup_weights<<<4, 256>>>(w);

    void* staging_addr = nullptr;
    cudaGetSymbolAddress(&staging_addr, g_staging);
    cudaMemcpyToSymbolAsync(cw2, staging_addr, NPAD * sizeof(u64), 0,
                            cudaMemcpyDeviceToDevice, 0);

    const int threads = 256;
    const int blocks  = HALF / threads;   // 1152
    gmm2_kernel<<<blocks, threads>>>(frames, mu0, (float*)d_out);
}

// round 11
// speedup vs baseline: 1.1138x; 1.1138x over previous
#include <cuda_runtime.h>

// ---------------------------------------------------------------------------
// GMMNet, 2 pixels/thread, packed f32x2 (FFMA2).
// R11 = R6 exact math + codegen (scalar LDCU.64 weight stream, tanh sigmoids,
// folded weights) with block=288 and PLAIN __launch_bounds__(288) (no
// min-blocks hint -> natural ~108 regs -> 2 CTAs x 288 = 18 warps/SM).
// ---------------------------------------------------------------------------

typedef unsigned long long u64;

namespace {
constexpr int Bn = 4, Sn = 8, Cn = 3, Hn = 384, Wn = 384, Kn = 5, CKn = 15;
constexpr int HWn  = Hn * Wn;            // 147456
constexpr int NPIX = Bn * HWn;           // 589824
constexpr int HALF = NPIX / 2;           // 294912

constexpr int PI_W1 = 0,   PI_B1 = 50,  PI_W2 = 55,  PI_B2 = 80;
constexpr int MU_W1 = 85,  MU_B1 = 430, MU_W2 = 445, MU_B2 = 670;
constexpr int SG_W1 = 685, SG_B1 = 800, SG_W2 = 805, SG_B2 = 830;
constexpr int GA_W1 = 835, GA_B1 = 860, GA_W2 = 865, GA_B2 = 870;
constexpr int NWTS  = 871;

constexpr float L2E = 1.4426950408889634f;
}

__constant__ u64 cw2[NWTS];
__device__   u64 g_staging[NWTS];

// ---- packed helpers ---------------------------------------------------------
__device__ __forceinline__ u64 pk(float lo, float hi) {
    u64 r; asm("mov.b64 %0, {%1, %2};" : "=l"(r) : "f"(lo), "f"(hi)); return r;
}
__device__ __forceinline__ void upk(u64 v, float& lo, float& hi) {
    asm("mov.b64 {%0, %1}, %2;" : "=f"(lo), "=f"(hi) : "l"(v));
}
__device__ __forceinline__ u64 fma2(u64 a, u64 b, u64 c) {
    u64 d; asm("fma.rn.f32x2 %0, %1, %2, %3;" : "=l"(d) : "l"(a), "l"(b), "l"(c)); return d;
}
__device__ __forceinline__ u64 mul2(u64 a, u64 b) {
    u64 d; asm("mul.rn.f32x2 %0, %1, %2;" : "=l"(d) : "l"(a), "l"(b)); return d;
}
__device__ __forceinline__ u64 add2(u64 a, u64 b) {
    u64 d; asm("add.rn.f32x2 %0, %1, %2;" : "=l"(d) : "l"(a), "l"(b)); return d;
}
__device__ __forceinline__ float ex2f(float x) {
    float y; asm("ex2.approx.f32 %0, %1;" : "=f"(y) : "f"(x)); return y;
}
__device__ __forceinline__ float rcpf(float x) {
    float y; asm("rcp.approx.f32 %0, %1;" : "=f"(y) : "f"(x)); return y;
}
__device__ __forceinline__ float tanhf_a(float x) {
    float y; asm("tanh.approx.f32 %0, %1;" : "=f"(y) : "f"(x)); return y;
}
__device__ __forceinline__ u64 ex2_2(u64 x) {
    float lo, hi; upk(x, lo, hi); return pk(ex2f(lo), ex2f(hi));
}
__device__ __forceinline__ u64 rcp_2(u64 x) {
    float lo, hi; upk(x, lo, hi); return pk(rcpf(lo), rcpf(hi));
}
__device__ __forceinline__ u64 tanh_2(u64 x) {
    float lo, hi; upk(x, lo, hi); return pk(tanhf_a(lo), tanhf_a(hi));
}
__device__ __forceinline__ u64 relu2(u64 x) {
    float lo, hi; upk(x, lo, hi);
    return pk(fmaxf(lo, 0.f), fmaxf(hi, 0.f));
}
__device__ __forceinline__ u64 min0_2(u64 x) {
    float lo, hi; upk(x, lo, hi);
    return pk(fminf(lo, 0.f), fminf(hi, 0.f));
}

// ---- weight duplication + constant folding -----------------------------------
struct WPtrs { const float* p[16]; };

__global__ void dup_weights(WPtrs w) {
    const int i = blockIdx.x * blockDim.x + threadIdx.x;
    if (i >= NWTS) return;
    constexpr int off[17] = {PI_W1, PI_B1, PI_W2, PI_B2,
                             MU_W1, MU_B1, MU_W2, MU_B2,
                             SG_W1, SG_B1, SG_W2, SG_B2,
                             GA_W1, GA_B1, GA_W2, GA_B2, NWTS};
    int s = 0;
#pragma unroll
    for (int k = 1; k < 16; k++) if (i >= off[k]) s = k;
    float v = w.p[s][i - off[s]];
    //  pi  softmax exp:       * log2e   (exp -> ex2)
    //  mu  sigmoid via tanh:  * 0.5     (sigmoid(a) = 0.5*tanh(0.5a)+0.5)
    //  sg  exp(-relu(a)):     * -log2e  (-> ex2(min(a',0)))
    //  ga  sigmoid via tanh:  * 0.5
    if (s == 2 || s == 3)        v *=  L2E;    // PI_W2, PI_B2
    else if (s == 6 || s == 7)   v *=  0.5f;   // MU_W2, MU_B2
    else if (s == 10 || s == 11) v *= -L2E;    // SG_W2, SG_B2
    else if (s == 14 || s == 15) v *=  0.5f;   // GA_W2, GA_B2
    g_staging[i] = pk(v, v);
}

// ---- main kernel --------------------------------------------------------------
__global__ void __launch_bounds__(288)
gmm2_kernel(const float* __restrict__ frames,   // [B,S,C,H,W]
            const float* __restrict__ mu0,      // [B,CK,H,W]
            float* __restrict__ out)            // [B,S,1,H,W]
{
    const int t = blockIdx.x * blockDim.x + threadIdx.x;
    if (t >= HALF) return;

    const int b0 = t / HWn,  hw0 = t - b0 * HWn;
    const int p1 = t + HALF;
    const int b1 = p1 / HWn, hw1 = p1 - b1 * HWn;

    const float* f0 = frames + (b0 * Sn * Cn) * HWn + hw0;
    const float* f1 = frames + (b1 * Sn * Cn) * HWn + hw1;
    const float* m0 = mu0 + (b0 * CKn) * HWn + hw0;
    const float* m1 = mu0 + (b1 * CKn) * HWn + hw1;
    float* o0 = out + (b0 * Sn) * HWn + hw0;
    float* o1 = out + (b1 * Sn) * HWn + hw1;

    const u64 HALF2  = pk(0.5f, 0.5f);
    const u64 NEG12  = pk(-1.0f, -1.0f);
    const u64 C02    = pk(0.06349363593424097f, 0.06349363593424097f);   // (2pi)^-1.5
    const u64 NHL2E2 = pk(-0.7213475204444817f, -0.7213475204444817f);   // -0.5*log2e

    // carried state: pi, mu, r2s = -0.5*log2e/sigma^2, cf = C0/sigma^3
    u64 pi[Kn], mu[CKn], r2s[Kn], cf[Kn];
#pragma unroll
    for (int k = 0; k < Kn; k++) { pi[k] = pk(0.2f, 0.2f); r2s[k] = NHL2E2; cf[k] = C02; }
#pragma unroll
    for (int i = 0; i < CKn; i++) mu[i] = pk(m0[i * HWn], m1[i * HWn]);

    for (int s = 0; s < Sn; s++) {
        u64 x[Cn];
#pragma unroll
        for (int c = 0; c < Cn; c++)
            x[c] = pk(f0[(s * Cn + c) * HWn], f1[(s * Cn + c) * HWn]);

        // ---- density 1, alpha, rho ---------------------------------------
        u64 alpha[Kn], rho[Kn];
#pragma unroll
        for (int k = 0; k < Kn; k++) {
            u64 t0 = fma2(mu[k * Cn + 0], NEG12, x[0]);
            u64 d  = mul2(t0, t0);
            u64 t1 = fma2(mu[k * Cn + 1], NEG12, x[1]);
            d = fma2(t1, t1, d);
            u64 t2 = fma2(mu[k * Cn + 2], NEG12, x[2]);
            d = fma2(t2, t2, d);
            const u64 dens = mul2(cf[k], ex2_2(mul2(d, r2s[k])));
            alpha[k] = mul2(pi[k], dens);
            rho[k]   = mul2(alpha[k], dens);
        }

        // ---- pi MLP -> softmax (W2 pre-scaled by log2e) --------------------
        u64 hp[Kn];
#pragma unroll
        for (int o = 0; o < Kn; o++) {
            u64 a = cw2[PI_B1 + o];
#pragma unroll
            for (int i = 0; i < Kn; i++) a = fma2(cw2[PI_W1 + o * 10 + i],     pi[i],    a);
#pragma unroll
            for (int i = 0; i < Kn; i++) a = fma2(cw2[PI_W1 + o * 10 + 5 + i], alpha[i], a);
            hp[o] = relu2(a);
        }
        u64 pin[Kn], esum = 0ULL;
#pragma unroll
        for (int o = 0; o < Kn; o++) {
            u64 a = cw2[PI_B2 + o];
#pragma unroll
            for (int i = 0; i < Kn; i++) a = fma2(cw2[PI_W2 + o * 5 + i], hp[i], a);
            pin[o] = ex2_2(a);
            esum   = add2(esum, pin[o]);
        }
        {
            const u64 einv = rcp_2(esum);
#pragma unroll
            for (int k = 0; k < Kn; k++) pin[k] = mul2(pin[k], einv);
        }

        // ---- mu MLP -> sigmoid via tanh (W2 pre-scaled by 0.5) --------------
        u64 hm[CKn];
#pragma unroll
        for (int o = 0; o < CKn; o++) {
            const int base = MU_W1 + o * 23;
            u64 a = cw2[MU_B1 + o];
#pragma unroll
            for (int c = 0; c < Cn; c++)  a = fma2(cw2[base + c],      x[c],   a);
#pragma unroll
            for (int i = 0; i < CKn; i++) a = fma2(cw2[base + 3 + i],  mu[i],  a);
#pragma unroll
            for (int i = 0; i < Kn; i++)  a = fma2(cw2[base + 18 + i], rho[i], a);
            hm[o] = relu2(a);
        }
        u64 mun[CKn];
#pragma unroll
        for (int o = 0; o < CKn; o++) {
            u64 a = cw2[MU_B2 + o];
#pragma unroll
            for (int i = 0; i < CKn; i++) a = fma2(cw2[MU_W2 + o * 15 + i], hm[i], a);
            mun[o] = fma2(tanh_2(a), HALF2, HALF2);   // sigmoid
        }

        // ---- sigma MLP (W2 pre-scaled by -log2e): rinv = ex2(min(a',0)) ----
        u64 hs[Kn];
#pragma unroll
        for (int o = 0; o < Kn; o++) {
            const int base = SG_W1 + o * 23;
            u64 a = cw2[SG_B1 + o];
#pragma unroll
            for (int c = 0; c < Cn; c++)  a = fma2(cw2[base + c],      x[c],   a);
#pragma unroll
            for (int i = 0; i < CKn; i++) a = fma2(cw2[base + 3 + i],  mun[i], a);
#pragma unroll
            for (int i = 0; i < Kn; i++)  a = fma2(cw2[base + 18 + i], rho[i], a);
            hs[o] = relu2(a);
        }
#pragma unroll
        for (int o = 0; o < Kn; o++) {
            u64 a = cw2[SG_B2 + o];
#pragma unroll
            for (int i = 0; i < Kn; i++) a = fma2(cw2[SG_W2 + o * 5 + i], hs[i], a);
            const u64 rin = ex2_2(min0_2(a));       // 1/sigma
            const u64 rr  = mul2(rin, rin);         // 1/sigma^2
            r2s[o] = mul2(rr, NHL2E2);
            cf[o]  = mul2(mul2(rin, C02), rr);      // C0/sigma^3
        }

        // ---- density 2, g = pi_new * dens2 ----------------------------------
        u64 g[Kn];
#pragma unroll
        for (int k = 0; k < Kn; k++) {
            u64 t0 = fma2(mun[k * Cn + 0], NEG12, x[0]);
            u64 d  = mul2(t0, t0);
            u64 t1 = fma2(mun[k * Cn + 1], NEG12, x[1]);
            d = fma2(t1, t1, d);
            u64 t2 = fma2(mun[k * Cn + 2], NEG12, x[2]);
            d = fma2(t2, t2, d);
            g[k] = mul2(pin[k], mul2(cf[k], ex2_2(mul2(d, r2s[k]))));
        }

        // ---- gamma MLP -> sigmoid via tanh (W2/B2 pre-scaled by 0.5) ---------
        u64 hg[Kn];
#pragma unroll
        for (int o = 0; o < Kn; o++) {
            u64 a = cw2[GA_B1 + o];
#pragma unroll
            for (int i = 0; i < Kn; i++) a = fma2(cw2[GA_W1 + o * 5 + i], g[i], a);
            hg[o] = relu2(a);
        }
        u64 ga = cw2[GA_B2];
#pragma unroll
        for (int i = 0; i < Kn; i++) ga = fma2(cw2[GA_W2 + i], hg[i], ga);
        {
            float al, ah; upk(ga, al, ah);
            o0[s * HWn] = fmaf(tanhf_a(al), 0.5f, 0.5f);
            o1[s * HWn] = fmaf(tanhf_a(ah), 0.5f, 0.5f);
        }

        // ---- carry -----------------------------------------------------------
#pragma unroll
        for (int k = 0; k < Kn; k++)  pi[k] = pin[k];
#pragma unroll
        for (int i = 0; i < CKn; i++) mu[i] = mun[i];
    }
}

extern "C" void kernel_launch(void* const* d_in, const int* in_sizes, int n_in,
                              void* d_out, int out_size)
{
    (void)in_sizes; (void)n_in; (void)out_size;
    const float* frames = (const float*)d_in[0];
    const float* mu0    = (const float*)d_in[2];   // d_in[1] = targets (unused)

    WPtrs w;
    for (int i = 0; i < 16; i++) w.p[i] = (const float*)d_in[3 + i];

    dup_weights<<<4, 256>>>(w);

    void* staging_addr = nullptr;
    cudaGetSymbolAddress(&staging_addr, g_staging);
    cudaMemcpyToSymbolAsync(cw2, staging_addr, NWTS * sizeof(u64), 0,
                            cudaMemcpyDeviceToDevice, 0);

    const int threads = 288;
    const int blocks  = HALF / threads;   // 1024
    gmm2_kernel<<<blocks, threads>>>(frames, mu0, (float*)d_out);
}

// round 12
// speedup vs baseline: 1.4961x; 1.3432x over previous
#include <cuda_runtime.h>

// ---------------------------------------------------------------------------
// GMMNet, 2 pixels/thread, packed f32x2 (FFMA2).
// R12 = R6 math, but carried sigma-state trimmed to rin[5] only (r2/coef
// recomputed in the density blocks) to drop natural regs ~108 -> ~98,
// then __launch_bounds__(128,5): cap 102, alloc step 96 -> 640 thr = 20 warps.
// ---------------------------------------------------------------------------

typedef unsigned long long u64;

namespace {
constexpr int Bn = 4, Sn = 8, Cn = 3, Hn = 384, Wn = 384, Kn = 5, CKn = 15;
constexpr int HWn  = Hn * Wn;            // 147456
constexpr int NPIX = Bn * HWn;           // 589824
constexpr int HALF = NPIX / 2;           // 294912

constexpr int PI_W1 = 0,   PI_B1 = 50,  PI_W2 = 55,  PI_B2 = 80;
constexpr int MU_W1 = 85,  MU_B1 = 430, MU_W2 = 445, MU_B2 = 670;
constexpr int SG_W1 = 685, SG_B1 = 800, SG_W2 = 805, SG_B2 = 830;
constexpr int GA_W1 = 835, GA_B1 = 860, GA_W2 = 865, GA_B2 = 870;
constexpr int NWTS  = 871;

constexpr float L2E = 1.4426950408889634f;
}

__constant__ u64 cw2[NWTS];
__device__   u64 g_staging[NWTS];

// ---- packed helpers ---------------------------------------------------------
__device__ __forceinline__ u64 pk(float lo, float hi) {
    u64 r; asm("mov.b64 %0, {%1, %2};" : "=l"(r) : "f"(lo), "f"(hi)); return r;
}
__device__ __forceinline__ void upk(u64 v, float& lo, float& hi) {
    asm("mov.b64 {%0, %1}, %2;" : "=f"(lo), "=f"(hi) : "l"(v));
}
__device__ __forceinline__ u64 fma2(u64 a, u64 b, u64 c) {
    u64 d; asm("fma.rn.f32x2 %0, %1, %2, %3;" : "=l"(d) : "l"(a), "l"(b), "l"(c)); return d;
}
__device__ __forceinline__ u64 mul2(u64 a, u64 b) {
    u64 d; asm("mul.rn.f32x2 %0, %1, %2;" : "=l"(d) : "l"(a), "l"(b)); return d;
}
__device__ __forceinline__ u64 add2(u64 a, u64 b) {
    u64 d; asm("add.rn.f32x2 %0, %1, %2;" : "=l"(d) : "l"(a), "l"(b)); return d;
}
__device__ __forceinline__ float ex2f(float x) {
    float y; asm("ex2.approx.f32 %0, %1;" : "=f"(y) : "f"(x)); return y;
}
__device__ __forceinline__ float rcpf(float x) {
    float y; asm("rcp.approx.f32 %0, %1;" : "=f"(y) : "f"(x)); return y;
}
__device__ __forceinline__ float tanhf_a(float x) {
    float y; asm("tanh.approx.f32 %0, %1;" : "=f"(y) : "f"(x)); return y;
}
__device__ __forceinline__ u64 ex2_2(u64 x) {
    float lo, hi; upk(x, lo, hi); return pk(ex2f(lo), ex2f(hi));
}
__device__ __forceinline__ u64 rcp_2(u64 x) {
    float lo, hi; upk(x, lo, hi); return pk(rcpf(lo), rcpf(hi));
}
__device__ __forceinline__ u64 tanh_2(u64 x) {
    float lo, hi; upk(x, lo, hi); return pk(tanhf_a(lo), tanhf_a(hi));
}
__device__ __forceinline__ u64 relu2(u64 x) {
    float lo, hi; upk(x, lo, hi);
    return pk(fmaxf(lo, 0.f), fmaxf(hi, 0.f));
}
__device__ __forceinline__ u64 min0_2(u64 x) {
    float lo, hi; upk(x, lo, hi);
    return pk(fminf(lo, 0.f), fminf(hi, 0.f));
}

// ---- weight duplication + constant folding -----------------------------------
struct WPtrs { const float* p[16]; };

__global__ void dup_weights(WPtrs w) {
    const int i = blockIdx.x * blockDim.x + threadIdx.x;
    if (i >= NWTS) return;
    constexpr int off[17] = {PI_W1, PI_B1, PI_W2, PI_B2,
                             MU_W1, MU_B1, MU_W2, MU_B2,
                             SG_W1, SG_B1, SG_W2, SG_B2,
                             GA_W1, GA_B1, GA_W2, GA_B2, NWTS};
    int s = 0;
#pragma unroll
    for (int k = 1; k < 16; k++) if (i >= off[k]) s = k;
    float v = w.p[s][i - off[s]];
    if (s == 2 || s == 3)        v *=  L2E;    // PI_W2, PI_B2  (softmax exp->ex2)
    else if (s == 6 || s == 7)   v *=  0.5f;   // MU_W2, MU_B2  (sigmoid via tanh)
    else if (s == 10 || s == 11) v *= -L2E;    // SG_W2, SG_B2  (exp(-relu)->ex2 min0)
    else if (s == 14 || s == 15) v *=  0.5f;   // GA_W2, GA_B2  (sigmoid via tanh)
    g_staging[i] = pk(v, v);
}

// ---- main kernel --------------------------------------------------------------
__global__ void __launch_bounds__(128, 5)
gmm2_kernel(const float* __restrict__ frames,   // [B,S,C,H,W]
            const float* __restrict__ mu0,      // [B,CK,H,W]
            float* __restrict__ out)            // [B,S,1,H,W]
{
    const int t = blockIdx.x * blockDim.x + threadIdx.x;
    if (t >= HALF) return;

    const int b0 = t / HWn,  hw0 = t - b0 * HWn;
    const int p1 = t + HALF;
    const int b1 = p1 / HWn, hw1 = p1 - b1 * HWn;

    const float* f0 = frames + (b0 * Sn * Cn) * HWn + hw0;
    const float* f1 = frames + (b1 * Sn * Cn) * HWn + hw1;
    const float* m0 = mu0 + (b0 * CKn) * HWn + hw0;
    const float* m1 = mu0 + (b1 * CKn) * HWn + hw1;
    float* o0 = out + (b0 * Sn) * HWn + hw0;
    float* o1 = out + (b1 * Sn) * HWn + hw1;

    const u64 HALF2  = pk(0.5f, 0.5f);
    const u64 NEG12  = pk(-1.0f, -1.0f);
    const u64 C02    = pk(0.06349363593424097f, 0.06349363593424097f);   // (2pi)^-1.5
    const u64 NHL2E2 = pk(-0.7213475204444817f, -0.7213475204444817f);   // -0.5*log2e
    const u64 ONE2   = pk(1.0f, 1.0f);

    // carried state: pi[5], mu[15], rin[5] = 1/sigma  (25 u64)
    u64 pi[Kn], mu[CKn], rin[Kn];
#pragma unroll
    for (int k = 0; k < Kn; k++) { pi[k] = pk(0.2f, 0.2f); rin[k] = ONE2; }
#pragma unroll
    for (int i = 0; i < CKn; i++) mu[i] = pk(m0[i * HWn], m1[i * HWn]);

    for (int s = 0; s < Sn; s++) {
        u64 x[Cn];
#pragma unroll
        for (int c = 0; c < Cn; c++)
            x[c] = pk(f0[(s * Cn + c) * HWn], f1[(s * Cn + c) * HWn]);

        // ---- density 1, alpha, rho  (r2, coef recomputed from rin) ---------
        u64 alpha[Kn], rho[Kn];
#pragma unroll
        for (int k = 0; k < Kn; k++) {
            const u64 r  = rin[k];
            const u64 r2 = mul2(r, r);
            u64 t0 = fma2(mu[k * Cn + 0], NEG12, x[0]);
            u64 d  = mul2(t0, t0);
            u64 t1 = fma2(mu[k * Cn + 1], NEG12, x[1]);
            d = fma2(t1, t1, d);
            u64 t2 = fma2(mu[k * Cn + 2], NEG12, x[2]);
            d = fma2(t2, t2, d);
            const u64 e    = ex2_2(mul2(mul2(d, r2), NHL2E2));
            const u64 dens = mul2(mul2(mul2(r, C02), r2), e);   // C0*r^3*e
            alpha[k] = mul2(pi[k], dens);
            rho[k]   = mul2(alpha[k], dens);
        }

        // ---- pi MLP -> softmax (W2 pre-scaled by log2e) --------------------
        u64 hp[Kn];
#pragma unroll
        for (int o = 0; o < Kn; o++) {
            u64 a = cw2[PI_B1 + o];
#pragma unroll
            for (int i = 0; i < Kn; i++) a = fma2(cw2[PI_W1 + o * 10 + i],     pi[i],    a);
#pragma unroll
            for (int i = 0; i < Kn; i++) a = fma2(cw2[PI_W1 + o * 10 + 5 + i], alpha[i], a);
            hp[o] = relu2(a);
        }
        u64 pin[Kn], esum = 0ULL;
#pragma unroll
        for (int o = 0; o < Kn; o++) {
            u64 a = cw2[PI_B2 + o];
#pragma unroll
            for (int i = 0; i < Kn; i++) a = fma2(cw2[PI_W2 + o * 5 + i], hp[i], a);
            pin[o] = ex2_2(a);
            esum   = add2(esum, pin[o]);
        }
        {
            const u64 einv = rcp_2(esum);
#pragma unroll
            for (int k = 0; k < Kn; k++) pin[k] = mul2(pin[k], einv);
        }

        // ---- mu MLP -> sigmoid via tanh (W2 pre-scaled by 0.5) --------------
        u64 hm[CKn];
#pragma unroll
        for (int o = 0; o < CKn; o++) {
            const int base = MU_W1 + o * 23;
            u64 a = cw2[MU_B1 + o];
#pragma unroll
            for (int c = 0; c < Cn; c++)  a = fma2(cw2[base + c],      x[c],   a);
#pragma unroll
            for (int i = 0; i < CKn; i++) a = fma2(cw2[base + 3 + i],  mu[i],  a);
#pragma unroll
            for (int i = 0; i < Kn; i++)  a = fma2(cw2[base + 18 + i], rho[i], a);
            hm[o] = relu2(a);
        }
        u64 mun[CKn];
#pragma unroll
        for (int o = 0; o < CKn; o++) {
            u64 a = cw2[MU_B2 + o];
#pragma unroll
            for (int i = 0; i < CKn; i++) a = fma2(cw2[MU_W2 + o * 15 + i], hm[i], a);
            mun[o] = fma2(tanh_2(a), HALF2, HALF2);   // sigmoid
        }

        // ---- sigma MLP (W2 pre-scaled by -log2e): rin = ex2(min(a',0)) ------
        u64 hs[Kn];
#pragma unroll
        for (int o = 0; o < Kn; o++) {
            const int base = SG_W1 + o * 23;
            u64 a = cw2[SG_B1 + o];
#pragma unroll
            for (int c = 0; c < Cn; c++)  a = fma2(cw2[base + c],      x[c],   a);
#pragma unroll
            for (int i = 0; i < CKn; i++) a = fma2(cw2[base + 3 + i],  mun[i], a);
#pragma unroll
            for (int i = 0; i < Kn; i++)  a = fma2(cw2[base + 18 + i], rho[i], a);
            hs[o] = relu2(a);
        }
#pragma unroll
        for (int o = 0; o < Kn; o++) {
            u64 a = cw2[SG_B2 + o];
#pragma unroll
            for (int i = 0; i < Kn; i++) a = fma2(cw2[SG_W2 + o * 5 + i], hs[i], a);
            rin[o] = ex2_2(min0_2(a));       // 1/sigma
        }

        // ---- density 2, g = pi_new * dens2 ----------------------------------
        u64 g[Kn];
#pragma unroll
        for (int k = 0; k < Kn; k++) {
            const u64 r  = rin[k];
            const u64 r2 = mul2(r, r);
            u64 t0 = fma2(mun[k * Cn + 0], NEG12, x[0]);
            u64 d  = mul2(t0, t0);
            u64 t1 = fma2(mun[k * Cn + 1], NEG12, x[1]);
            d = fma2(t1, t1, d);
            u64 t2 = fma2(mun[k * Cn + 2], NEG12, x[2]);
            d = fma2(t2, t2, d);
            const u64 e = ex2_2(mul2(mul2(d, r2), NHL2E2));
            g[k] = mul2(pin[k], mul2(mul2(mul2(r, C02), r2), e));
        }

        // ---- gamma MLP -> sigmoid via tanh (W2/B2 pre-scaled by 0.5) ---------
        u64 hg[Kn];
#pragma unroll
        for (int o = 0; o < Kn; o++) {
            u64 a = cw2[GA_B1 + o];
#pragma unroll
            for (int i = 0; i < Kn; i++) a = fma2(cw2[GA_W1 + o * 5 + i], g[i], a);
            hg[o] = relu2(a);
        }
        u64 ga = cw2[GA_B2];
#pragma unroll
        for (int i = 0; i < Kn; i++) ga = fma2(cw2[GA_W2 + i], hg[i], ga);
        {
            float al, ah; upk(ga, al, ah);
            o0[s * HWn] = fmaf(tanhf_a(al), 0.5f, 0.5f);
            o1[s * HWn] = fmaf(tanhf_a(ah), 0.5f, 0.5f);
        }

        // ---- carry -----------------------------------------------------------
#pragma unroll
        for (int k = 0; k < Kn; k++)  pi[k] = pin[k];
#pragma unroll
        for (int i = 0; i < CKn; i++) mu[i] = mun[i];
    }
}

extern "C" void kernel_launch(void* const* d_in, const int* in_sizes, int n_in,
                              void* d_out, int out_size)
{
    (void)in_sizes; (void)n_in; (void)out_size;
    const float* frames = (const float*)d_in[0];
    const float* mu0    = (const float*)d_in[2];   // d_in[1] = targets (unused)

    WPtrs w;
    for (int i = 0; i < 16; i++) w.p[i] = (const float*)d_in[3 + i];

    dup_weights<<<4, 256>>>(w);

    void* staging_addr = nullptr;
    cudaGetSymbolAddress(&staging_addr, g_staging);
    cudaMemcpyToSymbolAsync(cw2, staging_addr, NWTS * sizeof(u64), 0,
                            cudaMemcpyDeviceToDevice, 0);

    const int threads = 128;
    const int blocks  = HALF / threads;   // 2304
    gmm2_kernel<<<blocks, threads>>>(frames, mu0, (float*)d_out);
}

// round 13
// speedup vs baseline: 1.7924x; 1.1981x over previous
#include <cuda_runtime.h>

// ---------------------------------------------------------------------------
// GMMNet, 2 pixels/thread, packed f32x2 (FFMA2).
// R13 = R6 exact math/codegen/launch (scalar LDCU.64 weights, tanh sigmoids,
// folded weights, 256 thr, 108-reg class) + software prefetch of the next
// frame's x (double-buffered) to hide the loop-head LDG latency.
// ---------------------------------------------------------------------------

typedef unsigned long long u64;

namespace {
constexpr int Bn = 4, Sn = 8, Cn = 3, Hn = 384, Wn = 384, Kn = 5, CKn = 15;
constexpr int HWn  = Hn * Wn;            // 147456
constexpr int NPIX = Bn * HWn;           // 589824
constexpr int HALF = NPIX / 2;           // 294912

constexpr int PI_W1 = 0,   PI_B1 = 50,  PI_W2 = 55,  PI_B2 = 80;
constexpr int MU_W1 = 85,  MU_B1 = 430, MU_W2 = 445, MU_B2 = 670;
constexpr int SG_W1 = 685, SG_B1 = 800, SG_W2 = 805, SG_B2 = 830;
constexpr int GA_W1 = 835, GA_B1 = 860, GA_W2 = 865, GA_B2 = 870;
constexpr int NWTS  = 871;

constexpr float L2E = 1.4426950408889634f;
}

__constant__ u64 cw2[NWTS];
__device__   u64 g_staging[NWTS];

// ---- packed helpers ---------------------------------------------------------
__device__ __forceinline__ u64 pk(float lo, float hi) {
    u64 r; asm("mov.b64 %0, {%1, %2};" : "=l"(r) : "f"(lo), "f"(hi)); return r;
}
__device__ __forceinline__ void upk(u64 v, float& lo, float& hi) {
    asm("mov.b64 {%0, %1}, %2;" : "=f"(lo), "=f"(hi) : "l"(v));
}
__device__ __forceinline__ u64 fma2(u64 a, u64 b, u64 c) {
    u64 d; asm("fma.rn.f32x2 %0, %1, %2, %3;" : "=l"(d) : "l"(a), "l"(b), "l"(c)); return d;
}
__device__ __forceinline__ u64 mul2(u64 a, u64 b) {
    u64 d; asm("mul.rn.f32x2 %0, %1, %2;" : "=l"(d) : "l"(a), "l"(b)); return d;
}
__device__ __forceinline__ u64 add2(u64 a, u64 b) {
    u64 d; asm("add.rn.f32x2 %0, %1, %2;" : "=l"(d) : "l"(a), "l"(b)); return d;
}
__device__ __forceinline__ float ex2f(float x) {
    float y; asm("ex2.approx.f32 %0, %1;" : "=f"(y) : "f"(x)); return y;
}
__device__ __forceinline__ float rcpf(float x) {
    float y; asm("rcp.approx.f32 %0, %1;" : "=f"(y) : "f"(x)); return y;
}
__device__ __forceinline__ float tanhf_a(float x) {
    float y; asm("tanh.approx.f32 %0, %1;" : "=f"(y) : "f"(x)); return y;
}
__device__ __forceinline__ u64 ex2_2(u64 x) {
    float lo, hi; upk(x, lo, hi); return pk(ex2f(lo), ex2f(hi));
}
__device__ __forceinline__ u64 rcp_2(u64 x) {
    float lo, hi; upk(x, lo, hi); return pk(rcpf(lo), rcpf(hi));
}
__device__ __forceinline__ u64 tanh_2(u64 x) {
    float lo, hi; upk(x, lo, hi); return pk(tanhf_a(lo), tanhf_a(hi));
}
__device__ __forceinline__ u64 relu2(u64 x) {
    float lo, hi; upk(x, lo, hi);
    return pk(fmaxf(lo, 0.f), fmaxf(hi, 0.f));
}
__device__ __forceinline__ u64 min0_2(u64 x) {
    float lo, hi; upk(x, lo, hi);
    return pk(fminf(lo, 0.f), fminf(hi, 0.f));
}

// ---- weight duplication + constant folding -----------------------------------
struct WPtrs { const float* p[16]; };

__global__ void dup_weights(WPtrs w) {
    const int i = blockIdx.x * blockDim.x + threadIdx.x;
    if (i >= NWTS) return;
    constexpr int off[17] = {PI_W1, PI_B1, PI_W2, PI_B2,
                             MU_W1, MU_B1, MU_W2, MU_B2,
                             SG_W1, SG_B1, SG_W2, SG_B2,
                             GA_W1, GA_B1, GA_W2, GA_B2, NWTS};
    int s = 0;
#pragma unroll
    for (int k = 1; k < 16; k++) if (i >= off[k]) s = k;
    float v = w.p[s][i - off[s]];
    if (s == 2 || s == 3)        v *=  L2E;    // PI_W2, PI_B2  (softmax exp->ex2)
    else if (s == 6 || s == 7)   v *=  0.5f;   // MU_W2, MU_B2  (sigmoid via tanh)
    else if (s == 10 || s == 11) v *= -L2E;    // SG_W2, SG_B2  (exp(-relu)->ex2 min0)
    else if (s == 14 || s == 15) v *=  0.5f;   // GA_W2, GA_B2  (sigmoid via tanh)
    g_staging[i] = pk(v, v);
}

// ---- main kernel --------------------------------------------------------------
__global__ void __launch_bounds__(256)
gmm2_kernel(const float* __restrict__ frames,   // [B,S,C,H,W]
            const float* __restrict__ mu0,      // [B,CK,H,W]
            float* __restrict__ out)            // [B,S,1,H,W]
{
    const int t = blockIdx.x * blockDim.x + threadIdx.x;
    if (t >= HALF) return;

    const int b0 = t / HWn,  hw0 = t - b0 * HWn;
    const int p1 = t + HALF;
    const int b1 = p1 / HWn, hw1 = p1 - b1 * HWn;

    const float* f0 = frames + (b0 * Sn * Cn) * HWn + hw0;
    const float* f1 = frames + (b1 * Sn * Cn) * HWn + hw1;
    const float* m0 = mu0 + (b0 * CKn) * HWn + hw0;
    const float* m1 = mu0 + (b1 * CKn) * HWn + hw1;
    float* o0 = out + (b0 * Sn) * HWn + hw0;
    float* o1 = out + (b1 * Sn) * HWn + hw1;

    const u64 HALF2  = pk(0.5f, 0.5f);
    const u64 NEG12  = pk(-1.0f, -1.0f);
    const u64 C02    = pk(0.06349363593424097f, 0.06349363593424097f);   // (2pi)^-1.5
    const u64 NHL2E2 = pk(-0.7213475204444817f, -0.7213475204444817f);   // -0.5*log2e

    // carried state: pi, mu, r2s = -0.5*log2e/sigma^2, cf = C0/sigma^3
    u64 pi[Kn], mu[CKn], r2s[Kn], cf[Kn];
#pragma unroll
    for (int k = 0; k < Kn; k++) { pi[k] = pk(0.2f, 0.2f); r2s[k] = NHL2E2; cf[k] = C02; }
#pragma unroll
    for (int i = 0; i < CKn; i++) mu[i] = pk(m0[i * HWn], m1[i * HWn]);

    // prefetch frame 0 x
    u64 x[Cn];
#pragma unroll
    for (int c = 0; c < Cn; c++)
        x[c] = pk(f0[c * HWn], f1[c * HWn]);

    for (int s = 0; s < Sn; s++) {
        // issue next frame's loads immediately (clamped; full frame to cover)
        const int sn = (s + 1 < Sn) ? s + 1 : s;
        u64 xn[Cn];
#pragma unroll
        for (int c = 0; c < Cn; c++)
            xn[c] = pk(f0[(sn * Cn + c) * HWn], f1[(sn * Cn + c) * HWn]);

        // ---- density 1, alpha, rho ---------------------------------------
        u64 alpha[Kn], rho[Kn];
#pragma unroll
        for (int k = 0; k < Kn; k++) {
            u64 t0 = fma2(mu[k * Cn + 0], NEG12, x[0]);
            u64 d  = mul2(t0, t0);
            u64 t1 = fma2(mu[k * Cn + 1], NEG12, x[1]);
            d = fma2(t1, t1, d);
            u64 t2 = fma2(mu[k * Cn + 2], NEG12, x[2]);
            d = fma2(t2, t2, d);
            const u64 dens = mul2(cf[k], ex2_2(mul2(d, r2s[k])));
            alpha[k] = mul2(pi[k], dens);
            rho[k]   = mul2(alpha[k], dens);
        }

        // ---- pi MLP -> softmax (W2 pre-scaled by log2e) --------------------
        u64 hp[Kn];
#pragma unroll
        for (int o = 0; o < Kn; o++) {
            u64 a = cw2[PI_B1 + o];
#pragma unroll
            for (int i = 0; i < Kn; i++) a = fma2(cw2[PI_W1 + o * 10 + i],     pi[i],    a);
#pragma unroll
            for (int i = 0; i < Kn; i++) a = fma2(cw2[PI_W1 + o * 10 + 5 + i], alpha[i], a);
            hp[o] = relu2(a);
        }
        u64 pin[Kn], esum = 0ULL;
#pragma unroll
        for (int o = 0; o < Kn; o++) {
            u64 a = cw2[PI_B2 + o];
#pragma unroll
            for (int i = 0; i < Kn; i++) a = fma2(cw2[PI_W2 + o * 5 + i], hp[i], a);
            pin[o] = ex2_2(a);
            esum   = add2(esum, pin[o]);
        }
        {
            const u64 einv = rcp_2(esum);
#pragma unroll
            for (int k = 0; k < Kn; k++) pin[k] = mul2(pin[k], einv);
        }

        // ---- mu MLP -> sigmoid via tanh (W2 pre-scaled by 0.5) --------------
        u64 hm[CKn];
#pragma unroll
        for (int o = 0; o < CKn; o++) {
            const int base = MU_W1 + o * 23;
            u64 a = cw2[MU_B1 + o];
#pragma unroll
            for (int c = 0; c < Cn; c++)  a = fma2(cw2[base + c],      x[c],   a);
#pragma unroll
            for (int i = 0; i < CKn; i++) a = fma2(cw2[base + 3 + i],  mu[i],  a);
#pragma unroll
            for (int i = 0; i < Kn; i++)  a = fma2(cw2[base + 18 + i], rho[i], a);
            hm[o] = relu2(a);
        }
        u64 mun[CKn];
#pragma unroll
        for (int o = 0; o < CKn; o++) {
            u64 a = cw2[MU_B2 + o];
#pragma unroll
            for (int i = 0; i < CKn; i++) a = fma2(cw2[MU_W2 + o * 15 + i], hm[i], a);
            mun[o] = fma2(tanh_2(a), HALF2, HALF2);   // sigmoid
        }

        // ---- sigma MLP (W2 pre-scaled by -log2e): rinv = ex2(min(a',0)) ----
        u64 hs[Kn];
#pragma unroll
        for (int o = 0; o < Kn; o++) {
            const int base = SG_W1 + o * 23;
            u64 a = cw2[SG_B1 + o];
#pragma unroll
            for (int c = 0; c < Cn; c++)  a = fma2(cw2[base + c],      x[c],   a);
#pragma unroll
            for (int i = 0; i < CKn; i++) a = fma2(cw2[base + 3 + i],  mun[i], a);
#pragma unroll
            for (int i = 0; i < Kn; i++)  a = fma2(cw2[base + 18 + i], rho[i], a);
            hs[o] = relu2(a);
        }
#pragma unroll
        for (int o = 0; o < Kn; o++) {
            u64 a = cw2[SG_B2 + o];
#pragma unroll
            for (int i = 0; i < Kn; i++) a = fma2(cw2[SG_W2 + o * 5 + i], hs[i], a);
            const u64 rin = ex2_2(min0_2(a));       // 1/sigma
            const u64 rr  = mul2(rin, rin);         // 1/sigma^2
            r2s[o] = mul2(rr, NHL2E2);
            cf[o]  = mul2(mul2(rin, C02), rr);      // C0/sigma^3
        }

        // ---- density 2, g = pi_new * dens2 ----------------------------------
        u64 g[Kn];
#pragma unroll
        for (int k = 0; k < Kn; k++) {
            u64 t0 = fma2(mun[k * Cn + 0], NEG12, x[0]);
            u64 d  = mul2(t0, t0);
            u64 t1 = fma2(mun[k * Cn + 1], NEG12, x[1]);
            d = fma2(t1, t1, d);
            u64 t2 = fma2(mun[k * Cn + 2], NEG12, x[2]);
            d = fma2(t2, t2, d);
            g[k] = mul2(pin[k], mul2(cf[k], ex2_2(mul2(d, r2s[k]))));
        }

        // ---- gamma MLP -> sigmoid via tanh (W2/B2 pre-scaled by 0.5) ---------
        u64 hg[Kn];
#pragma unroll
        for (int o = 0; o < Kn; o++) {
            u64 a = cw2[GA_B1 + o];
#pragma unroll
            for (int i = 0; i < Kn; i++) a = fma2(cw2[GA_W1 + o * 5 + i], g[i], a);
            hg[o] = relu2(a);
        }
        u64 ga = cw2[GA_B2];
#pragma unroll
        for (int i = 0; i < Kn; i++) ga = fma2(cw2[GA_W2 + i], hg[i], ga);
        {
            float al, ah; upk(ga, al, ah);
            o0[s * HWn] = fmaf(tanhf_a(al), 0.5f, 0.5f);
            o1[s * HWn] = fmaf(tanhf_a(ah), 0.5f, 0.5f);
        }

        // ---- carry + buffer swap ----------------------------------------------
#pragma unroll
        for (int k = 0; k < Kn; k++)  pi[k] = pin[k];
#pragma unroll
        for (int i = 0; i < CKn; i++) mu[i] = mun[i];
#pragma unroll
        for (int c = 0; c < Cn; c++)  x[c] = xn[c];
    }
}

extern "C" void kernel_launch(void* const* d_in, const int* in_sizes, int n_in,
                              void* d_out, int out_size)
{
    (void)in_sizes; (void)n_in; (void)out_size;
    const float* frames = (const float*)d_in[0];
    const float* mu0    = (const float*)d_in[2];   // d_in[1] = targets (unused)

    WPtrs w;
    for (int i = 0; i < 16; i++) w.p[i] = (const float*)d_in[3 + i];

    dup_weights<<<4, 256>>>(w);

    void* staging_addr = nullptr;
    cudaGetSymbolAddress(&staging_addr, g_staging);
    cudaMemcpyToSymbolAsync(cw2, staging_addr, NWTS * sizeof(u64), 0,
                            cudaMemcpyDeviceToDevice, 0);

    const int threads = 256;
    const int blocks  = HALF / threads;   // 1152
    gmm2_kernel<<<blocks, threads>>>(frames, mu0, (float*)d_out);
}

// round 14
// speedup vs baseline: 1.7960x; 1.0020x over previous
#include <cuda_runtime.h>

// ---------------------------------------------------------------------------
// GMMNet, 2 pixels/thread, packed f32x2 (FFMA2).
// R14 = R13 (tanh sigmoids, folded weights, x-prefetch, 256 thr) +
// #pragma unroll 1 on the s-loop: keep ONE ~32KB body resident in L1.5 I$
// instead of streaming ~256KB of fully-unrolled straight-line code.
// ---------------------------------------------------------------------------

typedef unsigned long long u64;

namespace {
constexpr int Bn = 4, Sn = 8, Cn = 3, Hn = 384, Wn = 384, Kn = 5, CKn = 15;
constexpr int HWn  = Hn * Wn;            // 147456
constexpr int NPIX = Bn * HWn;           // 589824
constexpr int HALF = NPIX / 2;           // 294912

constexpr int PI_W1 = 0,   PI_B1 = 50,  PI_W2 = 55,  PI_B2 = 80;
constexpr int MU_W1 = 85,  MU_B1 = 430, MU_W2 = 445, MU_B2 = 670;
constexpr int SG_W1 = 685, SG_B1 = 800, SG_W2 = 805, SG_B2 = 830;
constexpr int GA_W1 = 835, GA_B1 = 860, GA_W2 = 865, GA_B2 = 870;
constexpr int NWTS  = 871;

constexpr float L2E = 1.4426950408889634f;
}

__constant__ u64 cw2[NWTS];
__device__   u64 g_staging[NWTS];

// ---- packed helpers ---------------------------------------------------------
__device__ __forceinline__ u64 pk(float lo, float hi) {
    u64 r; asm("mov.b64 %0, {%1, %2};" : "=l"(r) : "f"(lo), "f"(hi)); return r;
}
__device__ __forceinline__ void upk(u64 v, float& lo, float& hi) {
    asm("mov.b64 {%0, %1}, %2;" : "=f"(lo), "=f"(hi) : "l"(v));
}
__device__ __forceinline__ u64 fma2(u64 a, u64 b, u64 c) {
    u64 d; asm("fma.rn.f32x2 %0, %1, %2, %3;" : "=l"(d) : "l"(a), "l"(b), "l"(c)); return d;
}
__device__ __forceinline__ u64 mul2(u64 a, u64 b) {
    u64 d; asm("mul.rn.f32x2 %0, %1, %2;" : "=l"(d) : "l"(a), "l"(b)); return d;
}
__device__ __forceinline__ u64 add2(u64 a, u64 b) {
    u64 d; asm("add.rn.f32x2 %0, %1, %2;" : "=l"(d) : "l"(a), "l"(b)); return d;
}
__device__ __forceinline__ float ex2f(float x) {
    float y; asm("ex2.approx.f32 %0, %1;" : "=f"(y) : "f"(x)); return y;
}
__device__ __forceinline__ float rcpf(float x) {
    float y; asm("rcp.approx.f32 %0, %1;" : "=f"(y) : "f"(x)); return y;
}
__device__ __forceinline__ float tanhf_a(float x) {
    float y; asm("tanh.approx.f32 %0, %1;" : "=f"(y) : "f"(x)); return y;
}
__device__ __forceinline__ u64 ex2_2(u64 x) {
    float lo, hi; upk(x, lo, hi); return pk(ex2f(lo), ex2f(hi));
}
__device__ __forceinline__ u64 rcp_2(u64 x) {
    float lo, hi; upk(x, lo, hi); return pk(rcpf(lo), rcpf(hi));
}
__device__ __forceinline__ u64 tanh_2(u64 x) {
    float lo, hi; upk(x, lo, hi); return pk(tanhf_a(lo), tanhf_a(hi));
}
__device__ __forceinline__ u64 relu2(u64 x) {
    float lo, hi; upk(x, lo, hi);
    return pk(fmaxf(lo, 0.f), fmaxf(hi, 0.f));
}
__device__ __forceinline__ u64 min0_2(u64 x) {
    float lo, hi; upk(x, lo, hi);
    return pk(fminf(lo, 0.f), fminf(hi, 0.f));
}

// ---- weight duplication + constant folding -----------------------------------
struct WPtrs { const float* p[16]; };

__global__ void dup_weights(WPtrs w) {
    const int i = blockIdx.x * blockDim.x + threadIdx.x;
    if (i >= NWTS) return;
    constexpr int off[17] = {PI_W1, PI_B1, PI_W2, PI_B2,
                             MU_W1, MU_B1, MU_W2, MU_B2,
                             SG_W1, SG_B1, SG_W2, SG_B2,
                             GA_W1, GA_B1, GA_W2, GA_B2, NWTS};
    int s = 0;
#pragma unroll
    for (int k = 1; k < 16; k++) if (i >= off[k]) s = k;
    float v = w.p[s][i - off[s]];
    if (s == 2 || s == 3)        v *=  L2E;    // PI_W2, PI_B2  (softmax exp->ex2)
    else if (s == 6 || s == 7)   v *=  0.5f;   // MU_W2, MU_B2  (sigmoid via tanh)
    else if (s == 10 || s == 11) v *= -L2E;    // SG_W2, SG_B2  (exp(-relu)->ex2 min0)
    else if (s == 14 || s == 15) v *=  0.5f;   // GA_W2, GA_B2  (sigmoid via tanh)
    g_staging[i] = pk(v, v);
}

// ---- main kernel --------------------------------------------------------------
__global__ void __launch_bounds__(256)
gmm2_kernel(const float* __restrict__ frames,   // [B,S,C,H,W]
            const float* __restrict__ mu0,      // [B,CK,H,W]
            float* __restrict__ out)            // [B,S,1,H,W]
{
    const int t = blockIdx.x * blockDim.x + threadIdx.x;
    if (t >= HALF) return;

    const int b0 = t / HWn,  hw0 = t - b0 * HWn;
    const int p1 = t + HALF;
    const int b1 = p1 / HWn, hw1 = p1 - b1 * HWn;

    const float* f0 = frames + (b0 * Sn * Cn) * HWn + hw0;
    const float* f1 = frames + (b1 * Sn * Cn) * HWn + hw1;
    const float* m0 = mu0 + (b0 * CKn) * HWn + hw0;
    const float* m1 = mu0 + (b1 * CKn) * HWn + hw1;
    float* o0 = out + (b0 * Sn) * HWn + hw0;
    float* o1 = out + (b1 * Sn) * HWn + hw1;

    const u64 HALF2  = pk(0.5f, 0.5f);
    const u64 NEG12  = pk(-1.0f, -1.0f);
    const u64 C02    = pk(0.06349363593424097f, 0.06349363593424097f);   // (2pi)^-1.5
    const u64 NHL2E2 = pk(-0.7213475204444817f, -0.7213475204444817f);   // -0.5*log2e

    // carried state: pi, mu, r2s = -0.5*log2e/sigma^2, cf = C0/sigma^3
    u64 pi[Kn], mu[CKn], r2s[Kn], cf[Kn];
#pragma unroll
    for (int k = 0; k < Kn; k++) { pi[k] = pk(0.2f, 0.2f); r2s[k] = NHL2E2; cf[k] = C02; }
#pragma unroll
    for (int i = 0; i < CKn; i++) mu[i] = pk(m0[i * HWn], m1[i * HWn]);

    // prefetch frame 0 x
    u64 x[Cn];
#pragma unroll
    for (int c = 0; c < Cn; c++)
        x[c] = pk(f0[c * HWn], f1[c * HWn]);

#pragma unroll 1
    for (int s = 0; s < Sn; s++) {
        // issue next frame's loads immediately (clamped; full frame to cover)
        const int sn = (s + 1 < Sn) ? s + 1 : s;
        u64 xn[Cn];
#pragma unroll
        for (int c = 0; c < Cn; c++)
            xn[c] = pk(f0[(sn * Cn + c) * HWn], f1[(sn * Cn + c) * HWn]);

        // ---- density 1, alpha, rho ---------------------------------------
        u64 alpha[Kn], rho[Kn];
#pragma unroll
        for (int k = 0; k < Kn; k++) {
            u64 t0 = fma2(mu[k * Cn + 0], NEG12, x[0]);
            u64 d  = mul2(t0, t0);
            u64 t1 = fma2(mu[k * Cn + 1], NEG12, x[1]);
            d = fma2(t1, t1, d);
            u64 t2 = fma2(mu[k * Cn + 2], NEG12, x[2]);
            d = fma2(t2, t2, d);
            const u64 dens = mul2(cf[k], ex2_2(mul2(d, r2s[k])));
            alpha[k] = mul2(pi[k], dens);
            rho[k]   = mul2(alpha[k], dens);
        }

        // ---- pi MLP -> softmax (W2 pre-scaled by log2e) --------------------
        u64 hp[Kn];
#pragma unroll
        for (int o = 0; o < Kn; o++) {
            u64 a = cw2[PI_B1 + o];
#pragma unroll
            for (int i = 0; i < Kn; i++) a = fma2(cw2[PI_W1 + o * 10 + i],     pi[i],    a);
#pragma unroll
            for (int i = 0; i < Kn; i++) a = fma2(cw2[PI_W1 + o * 10 + 5 + i], alpha[i], a);
            hp[o] = relu2(a);
        }
        u64 pin[Kn], esum = 0ULL;
#pragma unroll
        for (int o = 0; o < Kn; o++) {
            u64 a = cw2[PI_B2 + o];
#pragma unroll
            for (int i = 0; i < Kn; i++) a = fma2(cw2[PI_W2 + o * 5 + i], hp[i], a);
            pin[o] = ex2_2(a);
            esum   = add2(esum, pin[o]);
        }
        {
            const u64 einv = rcp_2(esum);
#pragma unroll
            for (int k = 0; k < Kn; k++) pin[k] = mul2(pin[k], einv);
        }

        // ---- mu MLP -> sigmoid via tanh (W2 pre-scaled by 0.5) --------------
        u64 hm[CKn];
#pragma unroll
        for (int o = 0; o < CKn; o++) {
            const int base = MU_W1 + o * 23;
            u64 a = cw2[MU_B1 + o];
#pragma unroll
            for (int c = 0; c < Cn; c++)  a = fma2(cw2[base + c],      x[c],   a);
#pragma unroll
            for (int i = 0; i < CKn; i++) a = fma2(cw2[base + 3 + i],  mu[i],  a);
#pragma unroll
            for (int i = 0; i < Kn; i++)  a = fma2(cw2[base + 18 + i], rho[i], a);
            hm[o] = relu2(a);
        }
        u64 mun[CKn];
#pragma unroll
        for (int o = 0; o < CKn; o++) {
            u64 a = cw2[MU_B2 + o];
#pragma unroll
            for (int i = 0; i < CKn; i++) a = fma2(cw2[MU_W2 + o * 15 + i], hm[i], a);
            mun[o] = fma2(tanh_2(a), HALF2, HALF2);   // sigmoid
        }

        // ---- sigma MLP (W2 pre-scaled by -log2e): rinv = ex2(min(a',0)) ----
        u64 hs[Kn];
#pragma unroll
        for (int o = 0; o < Kn; o++) {
            const int base = SG_W1 + o * 23;
            u64 a = cw2[SG_B1 + o];
#pragma unroll
            for (int c = 0; c < Cn; c++)  a = fma2(cw2[base + c],      x[c],   a);
#pragma unroll
            for (int i = 0; i < CKn; i++) a = fma2(cw2[base + 3 + i],  mun[i], a);
#pragma unroll
            for (int i = 0; i < Kn; i++)  a = fma2(cw2[base + 18 + i], rho[i], a);
            hs[o] = relu2(a);
        }
#pragma unroll
        for (int o = 0; o < Kn; o++) {
            u64 a = cw2[SG_B2 + o];
#pragma unroll
            for (int i = 0; i < Kn; i++) a = fma2(cw2[SG_W2 + o * 5 + i], hs[i], a);
            const u64 rin = ex2_2(min0_2(a));       // 1/sigma
            const u64 rr  = mul2(rin, rin);         // 1/sigma^2
            r2s[o] = mul2(rr, NHL2E2);
            cf[o]  = mul2(mul2(rin, C02), rr);      // C0/sigma^3
        }

        // ---- density 2, g = pi_new * dens2 ----------------------------------
        u64 g[Kn];
#pragma unroll
        for (int k = 0; k < Kn; k++) {
            u64 t0 = fma2(mun[k * Cn + 0], NEG12, x[0]);
            u64 d  = mul2(t0, t0);
            u64 t1 = fma2(mun[k * Cn + 1], NEG12, x[1]);
            d = fma2(t1, t1, d);
            u64 t2 = fma2(mun[k * Cn + 2], NEG12, x[2]);
            d = fma2(t2, t2, d);
            g[k] = mul2(pin[k], mul2(cf[k], ex2_2(mul2(d, r2s[k]))));
        }

        // ---- gamma MLP -> sigmoid via tanh (W2/B2 pre-scaled by 0.5) ---------
        u64 hg[Kn];
#pragma unroll
        for (int o = 0; o < Kn; o++) {
            u64 a = cw2[GA_B1 + o];
#pragma unroll
            for (int i = 0; i < Kn; i++) a = fma2(cw2[GA_W1 + o * 5 + i], g[i], a);
            hg[o] = relu2(a);
        }
        u64 ga = cw2[GA_B2];
#pragma unroll
        for (int i = 0; i < Kn; i++) ga = fma2(cw2[GA_W2 + i], hg[i], ga);
        {
            float al, ah; upk(ga, al, ah);
            o0[s * HWn] = fmaf(tanhf_a(al), 0.5f, 0.5f);
            o1[s * HWn] = fmaf(tanhf_a(ah), 0.5f, 0.5f);
        }

        // ---- carry + buffer swap ----------------------------------------------
#pragma unroll
        for (int k = 0; k < Kn; k++)  pi[k] = pin[k];
#pragma unroll
        for (int i = 0; i < CKn; i++) mu[i] = mun[i];
#pragma unroll
        for (int c = 0; c < Cn; c++)  x[c] = xn[c];
    }
}

extern "C" void kernel_launch(void* const* d_in, const int* in_sizes, int n_in,
                              void* d_out, int out_size)
{
    (void)in_sizes; (void)n_in; (void)out_size;
    const float* frames = (const float*)d_in[0];
    const float* mu0    = (const float*)d_in[2];   // d_in[1] = targets (unused)

    WPtrs w;
    for (int i = 0; i < 16; i++) w.p[i] = (const float*)d_in[3 + i];

    dup_weights<<<4, 256>>>(w);

    void* staging_addr = nullptr;
    cudaGetSymbolAddress(&staging_addr, g_staging);
    cudaMemcpyToSymbolAsync(cw2, staging_addr, NWTS * sizeof(u64), 0,
                            cudaMemcpyDeviceToDevice, 0);

    const int threads = 256;
    const int blocks  = HALF / threads;   // 1152
    gmm2_kernel<<<blocks, threads>>>(frames, mu0, (float*)d_out);
}